// round 3
// baseline (speedup 1.0000x reference)
#include <cuda_runtime.h>
#include <math.h>

#define NBLK 128
#define NTHR 256

// shared memory layout (float offsets)
constexpr int O_W1 = 0;            // [64][128]  W1^T  (d, w)
constexpr int O_W2 = 8192;         // [128][128] W2^T  (k, w)
constexpr int O_W3 = 24576;        // [128][64]  W3^T  (w, d)
constexpr int O_KT = 32768;        // [64][64]   Kt    (d2, d)
constexpr int O_B1 = 36864;        // [128]
constexpr int O_B2 = 36992;        // [128]
constexpr int O_B3 = 37120;        // [64]
constexpr int O_TS = 37184;        // [128]
constexpr int O_YS = 37312;        // [64][36]  stage input z, transposed (d, m)
constexpr int O_H1 = 39616;        // [128][36] h1, transposed (w, m)
constexpr int O_H2 = 44224;        // [128][36] h2, transposed (w, m)
constexpr int SM_FLOATS = 48832;
constexpr int SMEM_BYTES = SM_FLOATS * 4;   // 195,328 B

__device__ float gW1t[64 * 128];
__device__ float gW2t[128 * 128];
__device__ float gW3t[128 * 64];
__device__ float gKt[64 * 64];

__global__ void setup_kernel(const float* __restrict__ W1, const float* __restrict__ W2,
                             const float* __restrict__ W3, const float* __restrict__ kvec,
                             const float* __restrict__ S, const int* __restrict__ sub) {
    int idx = blockIdx.x * blockDim.x + threadIdx.x;
    int stride = gridDim.x * blockDim.x;
    for (int i = idx; i < 64 * 128; i += stride) {           // W1 [128,64] -> W1t[d][w]
        int d = i >> 7, w = i & 127;
        gW1t[i] = W1[w * 64 + d];
    }
    for (int i = idx; i < 128 * 128; i += stride) {          // W2 [128,128] -> W2t[k][w]
        int c = i >> 7, w = i & 127;
        gW2t[i] = W2[w * 128 + c];
    }
    for (int i = idx; i < 128 * 64; i += stride) {           // W3 [64,128] -> W3t[w][d]
        int w = i >> 6, d = i & 63;
        gW3t[i] = W3[d * 128 + w];
    }
    // Kt[d2][d] = sum_{r: sub[r]==d2} S[d][r]*k[r]   (kin = z @ Kt)
    for (int i = idx; i < 64 * 64; i += stride) {
        int d2 = i >> 6, d = i & 63;
        float acc = 0.f;
        for (int r = 0; r < 128; ++r)
            if (sub[r] == d2) acc = fmaf(S[d * 128 + r], kvec[r], acc);
        gKt[i] = acc;
    }
}

struct F8 { float v[8]; };

// one vf eval for this CTA's 32 rows; stage input already in ysT (+synced).
// thread (lane, r0): rows r0..r0+3, cols {lane, lane+32}.
__device__ __noinline__ F8 vf_eval(int lane, int r0) {
    extern __shared__ float sm[];
    const float* ysT = sm + O_YS;
    float* h1T = sm + O_H1;
    float* h2T = sm + O_H2;
    float acc[4][4];

    // GEMM1: h1 = tanh(z @ W1^T + b1)   [32 x 128], K=64
#pragma unroll
    for (int j = 0; j < 4; ++j) {
        float bb = sm[O_B1 + lane + 32 * j];
#pragma unroll
        for (int i = 0; i < 4; ++i) acc[i][j] = bb;
    }
#pragma unroll 8
    for (int d = 0; d < 64; ++d) {
        float4 a = *(const float4*)(ysT + d * 36 + r0);
#pragma unroll
        for (int j = 0; j < 4; ++j) {
            float w = sm[O_W1 + d * 128 + lane + 32 * j];
            acc[0][j] = fmaf(a.x, w, acc[0][j]);
            acc[1][j] = fmaf(a.y, w, acc[1][j]);
            acc[2][j] = fmaf(a.z, w, acc[2][j]);
            acc[3][j] = fmaf(a.w, w, acc[3][j]);
        }
    }
#pragma unroll
    for (int j = 0; j < 4; ++j) {
        float4 t;
        t.x = tanhf(acc[0][j]); t.y = tanhf(acc[1][j]);
        t.z = tanhf(acc[2][j]); t.w = tanhf(acc[3][j]);
        *(float4*)(h1T + (lane + 32 * j) * 36 + r0) = t;
    }
    __syncthreads();

    // GEMM2: h2 = tanh(h1 @ W2^T + b2)  [32 x 128], K=128
#pragma unroll
    for (int j = 0; j < 4; ++j) {
        float bb = sm[O_B2 + lane + 32 * j];
#pragma unroll
        for (int i = 0; i < 4; ++i) acc[i][j] = bb;
    }
#pragma unroll 8
    for (int c = 0; c < 128; ++c) {
        float4 a = *(const float4*)(h1T + c * 36 + r0);
#pragma unroll
        for (int j = 0; j < 4; ++j) {
            float w = sm[O_W2 + c * 128 + lane + 32 * j];
            acc[0][j] = fmaf(a.x, w, acc[0][j]);
            acc[1][j] = fmaf(a.y, w, acc[1][j]);
            acc[2][j] = fmaf(a.z, w, acc[2][j]);
            acc[3][j] = fmaf(a.w, w, acc[3][j]);
        }
    }
#pragma unroll
    for (int j = 0; j < 4; ++j) {
        float4 t;
        t.x = tanhf(acc[0][j]); t.y = tanhf(acc[1][j]);
        t.z = tanhf(acc[2][j]); t.w = tanhf(acc[3][j]);
        *(float4*)(h2T + (lane + 32 * j) * 36 + r0) = t;
    }
    __syncthreads();

    // GEMM3: node = h2 @ W3^T + b3 (K=128)  +  kin = z @ Kt (K=64)
    float r8[4][2];
#pragma unroll
    for (int j = 0; j < 2; ++j) {
        float bb = sm[O_B3 + lane + 32 * j];
#pragma unroll
        for (int i = 0; i < 4; ++i) r8[i][j] = bb;
    }
#pragma unroll 8
    for (int w = 0; w < 128; ++w) {
        float4 a = *(const float4*)(h2T + w * 36 + r0);
#pragma unroll
        for (int j = 0; j < 2; ++j) {
            float wv = sm[O_W3 + w * 64 + lane + 32 * j];
            r8[0][j] = fmaf(a.x, wv, r8[0][j]);
            r8[1][j] = fmaf(a.y, wv, r8[1][j]);
            r8[2][j] = fmaf(a.z, wv, r8[2][j]);
            r8[3][j] = fmaf(a.w, wv, r8[3][j]);
        }
    }
#pragma unroll 8
    for (int d2 = 0; d2 < 64; ++d2) {
        float4 a = *(const float4*)(ysT + d2 * 36 + r0);
#pragma unroll
        for (int j = 0; j < 2; ++j) {
            float kv = sm[O_KT + d2 * 64 + lane + 32 * j];
            r8[0][j] = fmaf(a.x, kv, r8[0][j]);
            r8[1][j] = fmaf(a.y, kv, r8[1][j]);
            r8[2][j] = fmaf(a.z, kv, r8[2][j]);
            r8[3][j] = fmaf(a.w, kv, r8[3][j]);
        }
    }
    F8 r;
#pragma unroll
    for (int i = 0; i < 4; ++i)
#pragma unroll
        for (int j = 0; j < 2; ++j) r.v[i * 2 + j] = r8[i][j];
    return r;
}

template <typename F>
__device__ __forceinline__ void write_z(int lane, int r0, F f) {
    extern __shared__ float sm[];
    float* ysT = sm + O_YS;
#pragma unroll
    for (int j = 0; j < 2; ++j) {
        float4 zv;
        zv.x = f(0, j); zv.y = f(1, j); zv.z = f(2, j); zv.w = f(3, j);
        *(float4*)(ysT + (lane + 32 * j) * 36 + r0) = zv;
    }
}

__global__ void __launch_bounds__(NTHR, 1)
ode_kernel(const float* __restrict__ ts, const float* __restrict__ y0,
           const float* __restrict__ b1g, const float* __restrict__ b2g,
           const float* __restrict__ b3g, float* __restrict__ out) {
    extern __shared__ float sm[];
    int tid = threadIdx.x;

    for (int i = tid; i < 64 * 128; i += NTHR) sm[O_W1 + i] = gW1t[i];
    for (int i = tid; i < 128 * 128; i += NTHR) sm[O_W2 + i] = gW2t[i];
    for (int i = tid; i < 128 * 64; i += NTHR) sm[O_W3 + i] = gW3t[i];
    for (int i = tid; i < 64 * 64; i += NTHR) sm[O_KT + i] = gKt[i];
    if (tid < 128) {
        sm[O_B1 + tid] = b1g[tid];
        sm[O_B2 + tid] = b2g[tid];
        sm[O_TS + tid] = ts[tid];
    }
    if (tid < 64) sm[O_B3 + tid] = b3g[tid];

    const int lane = tid & 31;
    const int r0 = (tid >> 5) * 4;
    const int gm0 = blockIdx.x * 32 + r0;

    float y[4][2];
#pragma unroll
    for (int i = 0; i < 4; ++i)
#pragma unroll
        for (int j = 0; j < 2; ++j) {
            float v = y0[(gm0 + i) * 64 + lane + 32 * j];
            y[i][j] = v;
            out[(size_t)(gm0 + i) * 64 + lane + 32 * j] = v;
        }
    __syncthreads();

    for (int iv = 0; iv < 127; ++iv) {
        const float dtS = (sm[O_TS + iv + 1] - sm[O_TS + iv]) * 0.25f;

        for (int ss = 0; ss < 4; ++ss) {
            write_z(lane, r0, [&](int i, int j) { return y[i][j]; });
            __syncthreads();
            F8 K1 = vf_eval(lane, r0);
            __syncthreads();

            write_z(lane, r0, [&](int i, int j) {
                return fmaf(dtS, 0.161f * K1.v[2 * i + j], y[i][j]);
            });
            __syncthreads();
            F8 K2 = vf_eval(lane, r0);
            __syncthreads();

            write_z(lane, r0, [&](int i, int j) {
                int q = 2 * i + j;
                float s = fmaf(-0.008480655492356989f, K1.v[q],
                               0.335480655492357f * K2.v[q]);
                return fmaf(dtS, s, y[i][j]);
            });
            __syncthreads();
            F8 K3 = vf_eval(lane, r0);
            __syncthreads();

            write_z(lane, r0, [&](int i, int j) {
                int q = 2 * i + j;
                float s = 2.8971530571054935f * K1.v[q];
                s = fmaf(-6.359448489975075f, K2.v[q], s);
                s = fmaf(4.3622954328695815f, K3.v[q], s);
                return fmaf(dtS, s, y[i][j]);
            });
            __syncthreads();
            F8 K4 = vf_eval(lane, r0);
            __syncthreads();

            write_z(lane, r0, [&](int i, int j) {
                int q = 2 * i + j;
                float s = 5.325864828439257f * K1.v[q];
                s = fmaf(-11.748883564062828f, K2.v[q], s);
                s = fmaf(7.4955393428898365f, K3.v[q], s);
                s = fmaf(-0.09249506636175525f, K4.v[q], s);
                return fmaf(dtS, s, y[i][j]);
            });
            __syncthreads();
            F8 K5 = vf_eval(lane, r0);
            __syncthreads();

            write_z(lane, r0, [&](int i, int j) {
                int q = 2 * i + j;
                float s = 5.86145544294642f * K1.v[q];
                s = fmaf(-12.92096931784711f, K2.v[q], s);
                s = fmaf(8.159367898576159f, K3.v[q], s);
                s = fmaf(-0.071584973281401f, K4.v[q], s);
                s = fmaf(-0.028269050394068383f, K5.v[q], s);
                return fmaf(dtS, s, y[i][j]);
            });
            __syncthreads();
            F8 K6 = vf_eval(lane, r0);
            __syncthreads();

#pragma unroll
            for (int i = 0; i < 4; ++i)
#pragma unroll
                for (int j = 0; j < 2; ++j) {
                    int q = 2 * i + j;
                    float s = 0.09646076681806523f * K1.v[q];
                    s = fmaf(0.01f, K2.v[q], s);
                    s = fmaf(0.4798896504144996f, K3.v[q], s);
                    s = fmaf(1.379008574103742f, K4.v[q], s);
                    s = fmaf(-3.290069515436081f, K5.v[q], s);
                    s = fmaf(2.324710524099774f, K6.v[q], s);
                    y[i][j] = fmaf(dtS, s, y[i][j]);
                }
        }

        size_t base = (size_t)(iv + 1) * 4096 * 64;
#pragma unroll
        for (int i = 0; i < 4; ++i)
#pragma unroll
            for (int j = 0; j < 2; ++j)
                out[base + (gm0 + i) * 64 + lane + 32 * j] = y[i][j];
    }
}

extern "C" void kernel_launch(void* const* d_in, const int* in_sizes, int n_in,
                              void* d_out, int out_size) {
    const float* ts = (const float*)d_in[0];
    const float* y0 = (const float*)d_in[1];
    const float* W1 = (const float*)d_in[2];
    const float* b1 = (const float*)d_in[3];
    const float* W2 = (const float*)d_in[4];
    const float* b2 = (const float*)d_in[5];
    const float* W3 = (const float*)d_in[6];
    const float* b3 = (const float*)d_in[7];
    const float* k  = (const float*)d_in[8];
    const float* S  = (const float*)d_in[9];
    const int*   sub = (const int*)d_in[10];
    float* out = (float*)d_out;

    // idempotent, deterministic attribute set (also fine during capture)
    static bool attr_done = false;
    if (!attr_done) {
        cudaFuncSetAttribute(ode_kernel,
                             cudaFuncAttributeMaxDynamicSharedMemorySize,
                             SMEM_BYTES);
        attr_done = true;
    }

    setup_kernel<<<64, 256>>>(W1, W2, W3, k, S, sub);
    ode_kernel<<<NBLK, NTHR, SMEM_BYTES>>>(ts, y0, b1, b2, b3, out);
}